// round 11
// baseline (speedup 1.0000x reference)
#include <cuda_runtime.h>
#include <math.h>

#define NA 16384   // atoms
#define NM 1024    // molecules
#define NL 512     // labels
#define NS 1024    // substructures
#define HD 64      // hidden
#define BB 512     // batch
#define SSQ 32     // seq len
#define MAXDEG 128

// ---------------- scratch (device globals; no allocation allowed) -----------
__device__ int   g_cnt[NA];
__device__ int   g_cols[NA * MAXDEG];
__device__ float g_vals[NA * MAXDEG];
__device__ float g_h[NA * HD];      // h1 (layer-0 output)
__device__ float g_h2[NA * HD];     // h2 (layer-1 output)
__device__ float g_mol[NM * HD];
__device__ float g_emb[NL * HD];
__device__ float g_query[BB * HD];
__device__ float g_att[BB * NL];
__device__ float g_bipemb[BB * NS];
__device__ float g_weff[NS * NL];

// ---------------- weff + zero fused -----------------------------------------
// grid 2048 x 256 covers NS*NL = 524288; first 65536 threads also zero scratch
__global__ void k_weff_zero(const float* __restrict__ bo_w, const float* __restrict__ mask_H) {
    int i = blockIdx.x * blockDim.x + threadIdx.x;
    if (i < NA) g_cnt[i] = 0;
    if (i < NM * HD) g_mol[i] = 0.f;
    int s = i >> 9, l = i & (NL - 1);
    g_weff[i] = bo_w[i] * mask_H[l * NS + s];
}

// ---------------- bip_emb = query @ bt_w + bt_b (query inlined) -------------
// grid (BB/8, 2): x = batch tile of 8 rows, y = NS half. 512 threads.
__global__ void k_bipemb(const float* __restrict__ queries, const int* __restrict__ vmask,
                         const float* __restrict__ bt_w, const float* __restrict__ bt_b) {
    __shared__ float Qs[8][HD];
    __shared__ int lastv[8];
    int j = threadIdx.x;
    int half = blockIdx.y;
    int b0 = blockIdx.x * 8;
    if (j < 8) {
        const int* vm = vmask + (b0 + j) * SSQ;
        int s = 0;
        #pragma unroll
        for (int t = 0; t < SSQ; t++) s += (vm[t] != 0);
        lastv[j] = (s > 0) ? (s - 1) : 0;
    }
    __syncthreads();
    for (int i = j; i < 8 * HD; i += 512) {
        int r = i >> 6, c = i & 63;
        float q = queries[((long long)(b0 + r) * SSQ + lastv[r]) * HD + c];
        Qs[r][c] = q;
        if (half == 0) g_query[(b0 + r) * HD + c] = q;
    }
    __syncthreads();
    int col = half * 512 + j;
    float acc[8];
    float bz = bt_b[col];
    #pragma unroll
    for (int r = 0; r < 8; r++) acc[r] = bz;
    for (int k = 0; k < HD; k++) {
        float w = bt_w[k * NS + col];
        #pragma unroll
        for (int r = 0; r < 8; r++) acc[r] += Qs[r][k] * w;
    }
    #pragma unroll
    for (int r = 0; r < 8; r++) g_bipemb[(b0 + r) * NS + col] = acc[r];
}

// ---------------- layer 0: g_h = relu(embed[fp] @ W0 + b0) ------------------
__global__ void k_layer0(const float* __restrict__ W, const float* __restrict__ bias,
                         const int* __restrict__ fp, const float* __restrict__ embed) {
    __shared__ float Ws[HD * HD];
    __shared__ float Xs[4][HD];
    int tid = threadIdx.x;
    for (int i = tid; i < HD * HD; i += 256) Ws[i] = W[i];
    int r = tid >> 6, c = tid & 63;
    int row = blockIdx.x * 4 + r;
    Xs[r][c] = embed[fp[row] * HD + c];
    __syncthreads();
    float acc = bias[c];
    #pragma unroll
    for (int k = 0; k < HD; k++) acc += Xs[r][k] * Ws[k * HD + c];
    g_h[row * HD + c] = fmaxf(acc, 0.f);
}

// ---------------- sparse extraction of adj (1 GiB streaming read) -----------
// known-good config: 2048 blocks x 256 threads, 4 independent uint4 loads/iter
__device__ __forceinline__ void emit_nz(unsigned e, unsigned bits) {
    unsigned row = e >> 14;
    unsigned col = e & (NA - 1);
    int slot = atomicAdd(&g_cnt[row], 1);
    if (slot < MAXDEG) {
        g_cols[row * MAXDEG + slot] = (int)col;
        g_vals[row * MAXDEG + slot] = __uint_as_float(bits);
    }
}
__device__ __forceinline__ void proc4(uint4 v, unsigned idx4) {
    if ((v.x | v.y | v.z | v.w) != 0u) {
        unsigned e = idx4 * 4u;
        if (v.x) emit_nz(e,     v.x);
        if (v.y) emit_nz(e + 1, v.y);
        if (v.z) emit_nz(e + 2, v.z);
        if (v.w) emit_nz(e + 3, v.w);
    }
}
__global__ void k_extract(const uint4* __restrict__ adj4) {
    const unsigned TOTAL4 = (unsigned)NA * (NA / 4);   // 2^26
    unsigned stride = gridDim.x * blockDim.x;          // 2048*256 = 2^19
    unsigned i = blockIdx.x * blockDim.x + threadIdx.x;
    // TOTAL4 % (4*stride) == 0 -> exactly 32 iterations, no tail
    for (; i < TOTAL4; i += 4u * stride) {
        uint4 a = __ldcs(&adj4[i]);
        uint4 b = __ldcs(&adj4[i + stride]);
        uint4 c = __ldcs(&adj4[i + 2u * stride]);
        uint4 d = __ldcs(&adj4[i + 3u * stride]);
        proc4(a, i);
        proc4(b, i + stride);
        proc4(c, i + 2u * stride);
        proc4(d, i + 3u * stride);
    }
}

// ---------------- fused: fv1 = h1 + A h1 ; g_h2 = relu(fv1 @ W1 + b1) -------
__global__ void k_layer1_spmv(const float* __restrict__ W, const float* __restrict__ bias) {
    __shared__ float Ws[HD * HD];
    __shared__ float Xs[4][HD];
    int tid = threadIdx.x;
    if (tid < 128) {
        int w = tid >> 5, lane = tid & 31;
        int row = blockIdx.x * 4 + w;
        float a0 = g_h[row * HD + lane];
        float a1 = g_h[row * HD + 32 + lane];
        int cnt = min(g_cnt[row], MAXDEG);
        for (int n = 0; n < cnt; n++) {
            int   cc = g_cols[row * MAXDEG + n];
            float vv = g_vals[row * MAXDEG + n];
            a0 += vv * g_h[cc * HD + lane];
            a1 += vv * g_h[cc * HD + 32 + lane];
        }
        Xs[w][lane]      = a0;
        Xs[w][32 + lane] = a1;
    } else {
        int t = tid - 128;
        for (int i = t; i < HD * HD; i += 128) Ws[i] = W[i];
    }
    __syncthreads();
    int r = tid >> 6, c = tid & 63;
    int row = blockIdx.x * 4 + r;
    float acc = bias[c];
    #pragma unroll
    for (int k = 0; k < HD; k++) acc += Xs[r][k] * Ws[k * HD + c];
    g_h2[row * HD + c] = fmaxf(acc, 0.f);
}

// ---------------- fused: fv2 = h2 + A h2 ; segment-sum into g_mol -----------
__global__ void k_spmv_seg(const int* __restrict__ seg) {
    int warp = (blockIdx.x * blockDim.x + threadIdx.x) >> 5;
    int lane = threadIdx.x & 31;
    if (warp >= NA) return;
    float a0 = g_h2[warp * HD + lane];
    float a1 = g_h2[warp * HD + 32 + lane];
    int cnt = min(g_cnt[warp], MAXDEG);
    for (int n = 0; n < cnt; n++) {
        int   c = g_cols[warp * MAXDEG + n];
        float v = g_vals[warp * MAXDEG + n];
        a0 += v * g_h2[c * HD + lane];
        a1 += v * g_h2[c * HD + 32 + lane];
    }
    int m = seg[warp];
    atomicAdd(&g_mol[m * HD + lane],      a0);
    atomicAdd(&g_mol[m * HD + 32 + lane], a1);
}

// ---------------- mpnn_emb = avg_proj @ mol ([512,1024]@[1024,64]) ----------
// 128 blocks x 256 threads: 4 labels per block
__global__ void k_avgproj(const float* __restrict__ avg) {
    int r = threadIdx.x >> 6, c = threadIdx.x & 63;
    int l = blockIdx.x * 4 + r;
    const float* arow = avg + l * NM;
    float acc = 0.f;
    #pragma unroll 4
    for (int m = 0; m < NM; m++) acc += arow[m] * g_mol[m * HD + c];
    g_emb[l * HD + c] = acc;
}

// ---------------- fused match/out_w/layernorm: 4 rows/block, 128 blocks -----
__global__ void k_att(const float* __restrict__ out_w, const float* __restrict__ out_b,
                      const float* __restrict__ ln_g, const float* __restrict__ ln_b) {
    __shared__ float Qs[4][HD];
    __shared__ float Ms[4][NL];
    __shared__ float red[16];
    int l = threadIdx.x;
    int b0 = blockIdx.x * 4;
    for (int i = l; i < 4 * HD; i += 512) Qs[i >> 6][i & 63] = g_query[b0 * HD + i];
    __syncthreads();

    float e[HD];
    const float4* er = (const float4*)(g_emb + l * HD);
    #pragma unroll
    for (int k = 0; k < HD / 4; k++) {
        float4 t = er[k];
        e[4 * k] = t.x; e[4 * k + 1] = t.y; e[4 * k + 2] = t.z; e[4 * k + 3] = t.w;
    }
    float m[4];
    #pragma unroll
    for (int r = 0; r < 4; r++) {
        float acc = 0.f;
        #pragma unroll
        for (int k = 0; k < HD; k++) acc += Qs[r][k] * e[k];
        m[r] = 1.f / (1.f + __expf(-acc));
        Ms[r][l] = m[r];
    }
    __syncthreads();

    float acc[4];
    float ob = out_b[l];
    #pragma unroll
    for (int r = 0; r < 4; r++) acc[r] = m[r] + ob;
    for (int k = 0; k < NL; k++) {
        float w = out_w[k * NL + l];
        #pragma unroll
        for (int r = 0; r < 4; r++) acc[r] += Ms[r][k] * w;
    }

    float gg = ln_g[l], bbv = ln_b[l];
    int lane = l & 31, wid = l >> 5;
    for (int r = 0; r < 4; r++) {
        float v = acc[r];
        #pragma unroll
        for (int o = 16; o > 0; o >>= 1) v += __shfl_xor_sync(0xffffffffu, v, o);
        if (lane == 0) red[wid] = v;
        __syncthreads();
        if (l < 32) {
            float s = (l < 16) ? red[l] : 0.f;
            #pragma unroll
            for (int o = 8; o > 0; o >>= 1) s += __shfl_xor_sync(0xffffffffu, s, o);
            if (l == 0) red[0] = s;
        }
        __syncthreads();
        float mu = red[0] * (1.f / (float)NL);
        __syncthreads();
        float d = acc[r] - mu;
        v = d * d;
        #pragma unroll
        for (int o = 16; o > 0; o >>= 1) v += __shfl_xor_sync(0xffffffffu, v, o);
        if (lane == 0) red[wid] = v;
        __syncthreads();
        if (l < 32) {
            float s = (l < 16) ? red[l] : 0.f;
            #pragma unroll
            for (int o = 8; o > 0; o >>= 1) s += __shfl_xor_sync(0xffffffffu, s, o);
            if (l == 0) red[0] = s;
        }
        __syncthreads();
        float var = red[0] * (1.f / (float)NL);
        g_att[(b0 + r) * NL + l] = d * rsqrtf(var + 1e-5f) * gg + bbv;
        __syncthreads();
    }
}

// ---------------- final: sigmoid((bip_emb @ W_eff) * mpnn_att) --------------
// grid (BB/8, 2) x 256 threads: 8 rows, label half per block
__global__ void k_final(float* __restrict__ out) {
    __shared__ float Es[8][NS];   // 32 KB
    int t = threadIdx.x;
    int l = blockIdx.y * 256 + t;
    int b0 = blockIdx.x * 8;
    for (int i = t; i < 8 * NS; i += 256)
        Es[i >> 10][i & (NS - 1)] = g_bipemb[b0 * NS + i];
    __syncthreads();
    float acc[8] = {0, 0, 0, 0, 0, 0, 0, 0};
    for (int s = 0; s < NS; s++) {
        float w = g_weff[s * NL + l];
        #pragma unroll
        for (int r = 0; r < 8; r++) acc[r] += Es[r][s] * w;
    }
    #pragma unroll
    for (int r = 0; r < 8; r++) {
        float logit = acc[r] * g_att[(b0 + r) * NL + l];
        out[(b0 + r) * NL + l] = 1.f / (1.f + __expf(-logit));
    }
}

// ---------------- launch ------------------------------------------------------
extern "C" void kernel_launch(void* const* d_in, const int* in_sizes, int n_in,
                              void* d_out, int out_size) {
    const float* queries = (const float*)d_in[0];
    const int*   vmask   = (const int*)d_in[1];
    const float* embed   = (const float*)d_in[2];
    const float* W0w     = (const float*)d_in[3];
    const float* W0b     = (const float*)d_in[4];
    const float* W1w     = (const float*)d_in[5];
    const float* W1b     = (const float*)d_in[6];
    const float* adj     = (const float*)d_in[7];
    const float* avg     = (const float*)d_in[8];
    const float* maskH   = (const float*)d_in[9];
    const float* btw     = (const float*)d_in[10];
    const float* btb     = (const float*)d_in[11];
    const float* bow     = (const float*)d_in[12];
    const float* outw    = (const float*)d_in[13];
    const float* outb    = (const float*)d_in[14];
    const float* lng     = (const float*)d_in[15];
    const float* lnb     = (const float*)d_in[16];
    const int*   fp      = (const int*)d_in[17];
    const int*   seg     = (const int*)d_in[18];
    float*       out     = (float*)d_out;

    // sequential, single stream (fork measured as a regression on this
    // BW-bound pipeline)
    k_weff_zero  <<<(NS * NL) / 256, 256>>>(bow, maskH);        // 0
    k_bipemb     <<<dim3(BB / 8, 2), 512>>>(queries, vmask, btw, btb); // 1
    k_layer0     <<<NA / 4, 256>>>(W0w, W0b, fp, embed);        // 2
    k_extract    <<<2048, 256>>>((const uint4*)adj);            // 3 (dominant)
    k_layer1_spmv<<<NA / 4, 256>>>(W1w, W1b);                   // 4
    k_spmv_seg   <<<(NA * 32) / 256, 256>>>(seg);               // 5
    k_avgproj    <<<NL / 4, 256>>>(avg);                        // 6
    k_att        <<<BB / 4, 512>>>(outw, outb, lng, lnb);       // 7
    k_final      <<<dim3(BB / 8, 2), 256>>>(out);               // 8
}

// round 12
// speedup vs baseline: 1.1653x; 1.1653x over previous
#include <cuda_runtime.h>
#include <math.h>

#define NA 16384   // atoms
#define NM 1024    // molecules
#define NL 512     // labels
#define NS 1024    // substructures
#define HD 64      // hidden
#define BB 512     // batch
#define SSQ 32     // seq len
#define MAXDEG 128

// ---------------- scratch (device globals; no allocation allowed) -----------
__device__ int   g_cnt[NA];
__device__ int   g_cols[NA * MAXDEG];
__device__ float g_h[NA * HD];      // h1 (layer-0 output)
__device__ float g_h2[NA * HD];     // h2 (layer-1 output)
__device__ float g_mol[NM * HD];
__device__ float g_emb[NL * HD];
__device__ float g_query[BB * HD];
__device__ float g_att[BB * NL];
__device__ float g_bipemb[BB * NS];
__device__ float g_weff[NS * NL];

// ---------------- zero cnt + mol (main stream, precedes extract) ------------
__global__ void k_zero() {
    int i = blockIdx.x * blockDim.x + threadIdx.x;     // grid covers 65536
    if (i < NA) g_cnt[i] = 0;
    if (i < NM * HD) g_mol[i] = 0.f;
}

// ---------------- masked weight: W_eff[s][l] = bo_w[s][l]*mask_H[l][s] ------
__global__ void k_weff(const float* __restrict__ bo_w, const float* __restrict__ mask_H) {
    int i = blockIdx.x * blockDim.x + threadIdx.x;
    if (i < NS * NL) {
        int s = i >> 9, l = i & (NL - 1);
        g_weff[i] = bo_w[i] * mask_H[l * NS + s];
    }
}

// ---------------- bip_emb = query @ bt_w + bt_b (query inlined) -------------
// grid (BB/8, 2): x = batch tile of 8 rows, y = NS half. 512 threads.
__global__ void k_bipemb(const float* __restrict__ queries, const int* __restrict__ vmask,
                         const float* __restrict__ bt_w, const float* __restrict__ bt_b) {
    __shared__ float Qs[8][HD];
    __shared__ int lastv[8];
    int j = threadIdx.x;
    int half = blockIdx.y;
    int b0 = blockIdx.x * 8;
    if (j < 8) {
        const int* vm = vmask + (b0 + j) * SSQ;
        int s = 0;
        #pragma unroll
        for (int t = 0; t < SSQ; t++) s += (vm[t] != 0);
        lastv[j] = (s > 0) ? (s - 1) : 0;
    }
    __syncthreads();
    for (int i = j; i < 8 * HD; i += 512) {
        int r = i >> 6, c = i & 63;
        float q = queries[((long long)(b0 + r) * SSQ + lastv[r]) * HD + c];
        Qs[r][c] = q;
        if (half == 0) g_query[(b0 + r) * HD + c] = q;
    }
    __syncthreads();
    int col = half * 512 + j;
    float acc[8];
    float bz = bt_b[col];
    #pragma unroll
    for (int r = 0; r < 8; r++) acc[r] = bz;
    for (int k = 0; k < HD; k++) {
        float w = bt_w[k * NS + col];
        #pragma unroll
        for (int r = 0; r < 8; r++) acc[r] += Qs[r][k] * w;
    }
    #pragma unroll
    for (int r = 0; r < 8; r++) g_bipemb[(b0 + r) * NS + col] = acc[r];
}

// ---------------- layer 0: g_h = relu(embed[fp] @ W0 + b0) ------------------
__global__ void k_layer0(const float* __restrict__ W, const float* __restrict__ bias,
                         const int* __restrict__ fp, const float* __restrict__ embed) {
    __shared__ float Ws[HD * HD];
    __shared__ float Xs[4][HD];
    int tid = threadIdx.x;
    for (int i = tid; i < HD * HD; i += 256) Ws[i] = W[i];
    int r = tid >> 6, c = tid & 63;
    int row = blockIdx.x * 4 + r;
    Xs[r][c] = embed[fp[row] * HD + c];
    __syncthreads();
    float acc = bias[c];
    #pragma unroll
    for (int k = 0; k < HD; k++) acc += Xs[r][k] * Ws[k * HD + c];
    g_h[row * HD + c] = fmaxf(acc, 0.f);
}

// ---------------- sparse extraction of adj (1 GiB streaming read) -----------
// adj entries are exactly 0.0/1.0 -> store columns only (no values).
// profiled config: 2048x256, 4 independent uint4 loads/iter, 85% DRAM.
__device__ __forceinline__ void emit_nz(unsigned e) {
    unsigned row = e >> 14;
    unsigned col = e & (NA - 1);
    int slot = atomicAdd(&g_cnt[row], 1);
    if (slot < MAXDEG) g_cols[row * MAXDEG + slot] = (int)col;
}
__device__ __forceinline__ void proc4(uint4 v, unsigned idx4) {
    if ((v.x | v.y | v.z | v.w) != 0u) {
        unsigned e = idx4 * 4u;
        if (v.x) emit_nz(e);
        if (v.y) emit_nz(e + 1);
        if (v.z) emit_nz(e + 2);
        if (v.w) emit_nz(e + 3);
    }
}
__global__ void k_extract(const uint4* __restrict__ adj4) {
    const unsigned TOTAL4 = (unsigned)NA * (NA / 4);   // 2^26
    unsigned stride = gridDim.x * blockDim.x;          // 2048*256 = 2^19
    unsigned i = blockIdx.x * blockDim.x + threadIdx.x;
    // TOTAL4 % (4*stride) == 0 -> exactly 32 iterations, no tail
    for (; i < TOTAL4; i += 4u * stride) {
        uint4 a = __ldcs(&adj4[i]);
        uint4 b = __ldcs(&adj4[i + stride]);
        uint4 c = __ldcs(&adj4[i + 2u * stride]);
        uint4 d = __ldcs(&adj4[i + 3u * stride]);
        proc4(a, i);
        proc4(b, i + stride);
        proc4(c, i + 2u * stride);
        proc4(d, i + 3u * stride);
    }
}

// ---------------- fused: fv1 = h1 + A h1 ; g_h2 = relu(fv1 @ W1 + b1) -------
__global__ void k_layer1_spmv(const float* __restrict__ W, const float* __restrict__ bias) {
    __shared__ float Ws[HD * HD];
    __shared__ float Xs[4][HD];
    int tid = threadIdx.x;
    if (tid < 128) {
        int w = tid >> 5, lane = tid & 31;
        int row = blockIdx.x * 4 + w;
        float a0 = g_h[row * HD + lane];
        float a1 = g_h[row * HD + 32 + lane];
        int cnt = min(g_cnt[row], MAXDEG);
        for (int n = 0; n < cnt; n++) {
            int cc = g_cols[row * MAXDEG + n];
            a0 += g_h[cc * HD + lane];
            a1 += g_h[cc * HD + 32 + lane];
        }
        Xs[w][lane]      = a0;
        Xs[w][32 + lane] = a1;
    } else {
        int t = tid - 128;
        for (int i = t; i < HD * HD; i += 128) Ws[i] = W[i];
    }
    __syncthreads();
    int r = tid >> 6, c = tid & 63;
    int row = blockIdx.x * 4 + r;
    float acc = bias[c];
    #pragma unroll
    for (int k = 0; k < HD; k++) acc += Xs[r][k] * Ws[k * HD + c];
    g_h2[row * HD + c] = fmaxf(acc, 0.f);
}

// ---------------- fused: fv2 = h2 + A h2 ; segment-sum into g_mol -----------
__global__ void k_spmv_seg(const int* __restrict__ seg) {
    int warp = (blockIdx.x * blockDim.x + threadIdx.x) >> 5;
    int lane = threadIdx.x & 31;
    if (warp >= NA) return;
    float a0 = g_h2[warp * HD + lane];
    float a1 = g_h2[warp * HD + 32 + lane];
    int cnt = min(g_cnt[warp], MAXDEG);
    for (int n = 0; n < cnt; n++) {
        int c = g_cols[warp * MAXDEG + n];
        a0 += g_h2[c * HD + lane];
        a1 += g_h2[c * HD + 32 + lane];
    }
    int m = seg[warp];
    atomicAdd(&g_mol[m * HD + lane],      a0);
    atomicAdd(&g_mol[m * HD + 32 + lane], a1);
}

// ---------------- mpnn_emb = avg_proj @ mol ([512,1024]@[1024,64]) ----------
// 128 blocks x 256 threads: 4 labels per block
__global__ void k_avgproj(const float* __restrict__ avg) {
    int r = threadIdx.x >> 6, c = threadIdx.x & 63;
    int l = blockIdx.x * 4 + r;
    const float* arow = avg + l * NM;
    float acc = 0.f;
    #pragma unroll 4
    for (int m = 0; m < NM; m++) acc += arow[m] * g_mol[m * HD + c];
    g_emb[l * HD + c] = acc;
}

// ---------------- fused match/out_w/layernorm: 4 rows/block, 128 blocks -----
__global__ void k_att(const float* __restrict__ out_w, const float* __restrict__ out_b,
                      const float* __restrict__ ln_g, const float* __restrict__ ln_b) {
    __shared__ float Qs[4][HD];
    __shared__ float Ms[4][NL];
    __shared__ float red[16];
    int l = threadIdx.x;
    int b0 = blockIdx.x * 4;
    for (int i = l; i < 4 * HD; i += 512) Qs[i >> 6][i & 63] = g_query[b0 * HD + i];
    __syncthreads();

    float e[HD];
    const float4* er = (const float4*)(g_emb + l * HD);
    #pragma unroll
    for (int k = 0; k < HD / 4; k++) {
        float4 t = er[k];
        e[4 * k] = t.x; e[4 * k + 1] = t.y; e[4 * k + 2] = t.z; e[4 * k + 3] = t.w;
    }
    float m[4];
    #pragma unroll
    for (int r = 0; r < 4; r++) {
        float acc = 0.f;
        #pragma unroll
        for (int k = 0; k < HD; k++) acc += Qs[r][k] * e[k];
        m[r] = 1.f / (1.f + __expf(-acc));
        Ms[r][l] = m[r];
    }
    __syncthreads();

    float acc[4];
    float ob = out_b[l];
    #pragma unroll
    for (int r = 0; r < 4; r++) acc[r] = m[r] + ob;
    for (int k = 0; k < NL; k++) {
        float w = out_w[k * NL + l];
        #pragma unroll
        for (int r = 0; r < 4; r++) acc[r] += Ms[r][k] * w;
    }

    float gg = ln_g[l], bbv = ln_b[l];
    int lane = l & 31, wid = l >> 5;
    for (int r = 0; r < 4; r++) {
        float v = acc[r];
        #pragma unroll
        for (int o = 16; o > 0; o >>= 1) v += __shfl_xor_sync(0xffffffffu, v, o);
        if (lane == 0) red[wid] = v;
        __syncthreads();
        if (l < 32) {
            float s = (l < 16) ? red[l] : 0.f;
            #pragma unroll
            for (int o = 8; o > 0; o >>= 1) s += __shfl_xor_sync(0xffffffffu, s, o);
            if (l == 0) red[0] = s;
        }
        __syncthreads();
        float mu = red[0] * (1.f / (float)NL);
        __syncthreads();
        float d = acc[r] - mu;
        v = d * d;
        #pragma unroll
        for (int o = 16; o > 0; o >>= 1) v += __shfl_xor_sync(0xffffffffu, v, o);
        if (lane == 0) red[wid] = v;
        __syncthreads();
        if (l < 32) {
            float s = (l < 16) ? red[l] : 0.f;
            #pragma unroll
            for (int o = 8; o > 0; o >>= 1) s += __shfl_xor_sync(0xffffffffu, s, o);
            if (l == 0) red[0] = s;
        }
        __syncthreads();
        float var = red[0] * (1.f / (float)NL);
        g_att[(b0 + r) * NL + l] = d * rsqrtf(var + 1e-5f) * gg + bbv;
        __syncthreads();
    }
}

// ---------------- final: sigmoid((bip_emb @ W_eff) * mpnn_att) --------------
// grid (BB/16, 4) x 128 threads: 16 rows, label quarter per block.
// 64 KB dynamic smem for the bip_emb tile; weff L2 traffic = 64 MB total.
__global__ void k_final(float* __restrict__ out) {
    extern __shared__ float Es[];            // [16][NS]
    int t = threadIdx.x;                     // 0..127
    int l = blockIdx.y * 128 + t;
    int b0 = blockIdx.x * 16;
    const float4* src = (const float4*)(g_bipemb + b0 * NS);
    float4* dst = (float4*)Es;
    for (int i = t; i < 16 * NS / 4; i += 128) dst[i] = src[i];
    __syncthreads();
    float acc[16];
    #pragma unroll
    for (int r = 0; r < 16; r++) acc[r] = 0.f;
    for (int s = 0; s < NS; s++) {
        float w = g_weff[s * NL + l];
        #pragma unroll
        for (int r = 0; r < 16; r++) acc[r] += Es[r * NS + s] * w;
    }
    #pragma unroll
    for (int r = 0; r < 16; r++) {
        float logit = acc[r] * g_att[(b0 + r) * NL + l];
        out[(b0 + r) * NL + l] = 1.f / (1.f + __expf(-logit));
    }
}

// ---------------- launch ------------------------------------------------------
extern "C" void kernel_launch(void* const* d_in, const int* in_sizes, int n_in,
                              void* d_out, int out_size) {
    const float* queries = (const float*)d_in[0];
    const int*   vmask   = (const int*)d_in[1];
    const float* embed   = (const float*)d_in[2];
    const float* W0w     = (const float*)d_in[3];
    const float* W0b     = (const float*)d_in[4];
    const float* W1w     = (const float*)d_in[5];
    const float* W1b     = (const float*)d_in[6];
    const float* adj     = (const float*)d_in[7];
    const float* avg     = (const float*)d_in[8];
    const float* maskH   = (const float*)d_in[9];
    const float* btw     = (const float*)d_in[10];
    const float* btb     = (const float*)d_in[11];
    const float* bow     = (const float*)d_in[12];
    const float* outw    = (const float*)d_in[13];
    const float* outb    = (const float*)d_in[14];
    const float* lng     = (const float*)d_in[15];
    const float* lnb     = (const float*)d_in[16];
    const int*   fp      = (const int*)d_in[17];
    const int*   seg     = (const int*)d_in[18];
    float*       out     = (float*)d_out;

    // one-time host-side setup (first call is the uncaptured correctness run;
    // identical work is issued on every call)
    static cudaStream_t s2 = nullptr;
    static cudaEvent_t evFork = nullptr, evJoin = nullptr;
    if (s2 == nullptr) {
        cudaStreamCreateWithFlags(&s2, cudaStreamNonBlocking);
        cudaEventCreateWithFlags(&evFork, cudaEventDisableTiming);
        cudaEventCreateWithFlags(&evJoin, cudaEventDisableTiming);
        cudaFuncSetAttribute(k_final, cudaFuncAttributeMaxDynamicSharedMemorySize,
                             16 * NS * (int)sizeof(float));
    }

    // fork: query path runs concurrently with the BW-bound adj scan
    cudaEventRecord(evFork, 0);
    cudaStreamWaitEvent(s2, evFork, 0);

    k_layer0<<<NA / 4, 256, 0, s2>>>(W0w, W0b, fp, embed);          // s2
    k_bipemb<<<dim3(BB / 8, 2), 512, 0, s2>>>(queries, vmask, btw, btb);
    k_weff  <<<(NS * NL) / 256, 256, 0, s2>>>(bow, maskH);
    cudaEventRecord(evJoin, s2);

    // main: CSR build (dominant, ~160us @ 85% DRAM)
    k_zero   <<<256, 256>>>();
    k_extract<<<2048, 256>>>((const uint4*)adj);

    // join: layer1 needs g_h (s2) + CSR (main)
    cudaStreamWaitEvent(0, evJoin, 0);

    k_layer1_spmv<<<NA / 4, 256>>>(W1w, W1b);
    k_spmv_seg   <<<(NA * 32) / 256, 256>>>(seg);
    k_avgproj    <<<NL / 4, 256>>>(avg);
    k_att        <<<BB / 4, 512>>>(outw, outb, lng, lnb);
    k_final      <<<dim3(BB / 16, 4), 128, 16 * NS * sizeof(float)>>>(out);
}